// round 4
// baseline (speedup 1.0000x reference)
#include <cuda_runtime.h>
#include <math.h>

typedef unsigned long long ull;

// Problem dims
#define BB 64
#define NN 133
#define NROW (BB*NN)      // 8512 = M of all dense GEMMs
#define F0 75
#define F1 150
#define H1 256
#define H2 128

// ---------------- scratch ----------------
__device__ float g_bufA[(size_t)NROW * 256];
__device__ float g_bufB[(size_t)NROW * 256];

__device__ int   g_nz_cnt[NROW];
__device__ ull   g_nz[(size_t)NROW * NN];      // packed {val:hi32, idx:lo32}
__device__ int   g_pl_cnt[NROW];
__device__ int   g_pl_idx[(size_t)NROW * NN];

// ---------------- f32x2 helpers ----------------
__device__ __forceinline__ ull pk2(float x, float y) {
    ull r;
    asm("mov.b64 %0, {%1, %2};" : "=l"(r) : "f"(x), "f"(y));
    return r;
}
__device__ __forceinline__ void upk2(ull v, float& x, float& y) {
    asm("mov.b64 {%0, %1}, %2;" : "=f"(x), "=f"(y) : "l"(v));
}
#define FMA2(acc, a, b) asm("fma.rn.f32x2 %0, %1, %2, %0;" : "+l"(acc) : "l"(a), "l"(b))

// ---------------- build sparse lists from adj (warp per row) ----------------
__global__ void k_build_lists(const float* __restrict__ adj) {
    int warp_in_blk = threadIdx.x >> 5;
    int lane = threadIdx.x & 31;
    int wg = blockIdx.x * (blockDim.x >> 5) + warp_in_blk;
    if (wg >= NROW) return;
    const float* arow = adj + (size_t)wg * NN;

    int cnz = 0, cpl = 0;
    unsigned lt = (1u << lane) - 1u;
    for (int base = 0; base < NN; base += 32) {
        int j = base + lane;
        float a = (j < NN) ? arow[j] : 0.0f;
        bool nz = (j < NN) && (a != 0.0f);
        bool pl = (j < NN) && (a > 1e-5f);
        unsigned mnz = __ballot_sync(0xffffffffu, nz);
        unsigned mpl = __ballot_sync(0xffffffffu, pl);
        if (nz) {
            int pos = cnz + __popc(mnz & lt);
            g_nz[(size_t)wg * NN + pos] =
                ((ull)__float_as_uint(a) << 32) | (unsigned)j;
        }
        if (pl) {
            int pos = cpl + __popc(mpl & lt);
            g_pl_idx[(size_t)wg * NN + pos] = j;
        }
        cnz += __popc(mnz);
        cpl += __popc(mpl);
    }
    if (lane == 0) { g_nz_cnt[wg] = cnz; g_pl_cnt[wg] = cpl; }
}

// ---------------- register-tiled f32x2 SGEMM ----------------
// C[M,G] = A[M,K] @ W[K,G] (+bias, relu).  M = 8512 (flattened batch*nodes).
// BM=128, BN=64, KC=64. Block 128 thr (ty 0..15 -> 8 rows, tx 0..7 -> 8 cols).
// smem: sAT[KC][128] (A transposed), sW2[KC][64] (W duplicated into f32x2).
__global__ void k_gemm(const float* __restrict__ A, const float* __restrict__ W,
                       const float* __restrict__ bias, float* __restrict__ C,
                       int M, int K, int G, int do_relu) {
    const int KC = 64;
    extern __shared__ char smraw[];
    float* sAT = (float*)smraw;                    // [KC][128]  32KB
    ull*   sW2 = (ull*)(smraw + KC * 128 * 4);     // [KC][64]   32KB

    int t  = threadIdx.x;
    int tx = t & 7;
    int ty = t >> 3;
    int row0 = blockIdx.x * 128;
    int cb   = blockIdx.y * 64;

    ull acc[4][8];
    #pragma unroll
    for (int rp = 0; rp < 4; rp++)
        #pragma unroll
        for (int c = 0; c < 8; c++) acc[rp][c] = 0ull;

    for (int kc = 0; kc < K; kc += KC) {
        // fill sAT: idx -> (r, kk); consecutive t -> consecutive kk (coalesced)
        #pragma unroll
        for (int rep = 0; rep < 64; rep++) {
            int idx = rep * 128 + t;
            int r  = idx >> 6;          // /KC
            int kk = idx & 63;
            int k  = kc + kk;
            int row = row0 + r;
            sAT[kk * 128 + r] = (row < M && k < K) ? A[(size_t)row * K + k] : 0.0f;
        }
        // fill sW2: idx -> (kk, c); consecutive t -> consecutive c (coalesced)
        #pragma unroll
        for (int rep = 0; rep < 32; rep++) {
            int idx = rep * 128 + t;
            int kk = idx >> 6;
            int c  = idx & 63;
            int k  = kc + kk;
            int g  = cb + c;
            float w = (k < K && g < G) ? W[(size_t)k * G + g] : 0.0f;
            sW2[kk * 64 + c] = pk2(w, w);
        }
        __syncthreads();

        #pragma unroll 4
        for (int kk = 0; kk < KC; kk++) {
            ulonglong2 aa0 = *(const ulonglong2*)(sAT + kk * 128 + ty * 8);
            ulonglong2 aa1 = *(const ulonglong2*)(sAT + kk * 128 + ty * 8 + 4);
            const ulonglong2* wp = (const ulonglong2*)(sW2 + kk * 64 + tx * 8);
            ulonglong2 w01 = wp[0], w23 = wp[1], w45 = wp[2], w67 = wp[3];
            ull a2[4] = {aa0.x, aa0.y, aa1.x, aa1.y};
            ull w2[8] = {w01.x, w01.y, w23.x, w23.y, w45.x, w45.y, w67.x, w67.y};
            #pragma unroll
            for (int rp = 0; rp < 4; rp++)
                #pragma unroll
                for (int c = 0; c < 8; c++)
                    FMA2(acc[rp][c], a2[rp], w2[c]);
        }
        __syncthreads();
    }

    // epilogue: bias + relu + store
    #pragma unroll
    for (int c = 0; c < 8; c++) {
        int g = cb + tx * 8 + c;
        if (g >= G) continue;
        float bv = bias ? bias[g] : 0.0f;
        #pragma unroll
        for (int rp = 0; rp < 4; rp++) {
            float v0, v1;
            upk2(acc[rp][c], v0, v1);
            v0 += bv; v1 += bv;
            if (do_relu) { v0 = fmaxf(v0, 0.0f); v1 = fmaxf(v1, 0.0f); }
            int r0 = row0 + ty * 8 + rp * 2;
            if (r0 < M)     C[(size_t)r0 * G + g]       = v0;
            if (r0 + 1 < M) C[(size_t)(r0 + 1) * G + g] = v1;
        }
    }
}

// ---------------- spmm + relu, 4 cols/thread (LDG.128 gather) ----------------
// grid (ceil(NN/RPB), BB), block (G/4, RPB). G % 4 == 0.
__global__ void k_spmm4(const float* __restrict__ T, const float* __restrict__ bias,
                        float* __restrict__ O, int G) {
    int b = blockIdx.y;
    int i = blockIdx.x * blockDim.y + threadIdx.y;
    if (i >= NN) return;
    int row = b * NN + i;
    int g0 = threadIdx.x * 4;

    int cnt = g_nz_cnt[row];
    const ull* L = g_nz + (size_t)row * NN;
    const float* Tb = T + (size_t)b * NN * G + g0;

    ull acc0 = pk2(bias[g0], bias[g0 + 1]);
    ull acc1 = pk2(bias[g0 + 2], bias[g0 + 3]);
    int e = 0;
    for (; e + 2 <= cnt; e += 2) {
        ull p0 = L[e], p1 = L[e + 1];
        int j0 = (int)(unsigned)p0, j1 = (int)(unsigned)p1;
        ull v0 = pk2(__uint_as_float((unsigned)(p0 >> 32)), __uint_as_float((unsigned)(p0 >> 32)));
        ull v1 = pk2(__uint_as_float((unsigned)(p1 >> 32)), __uint_as_float((unsigned)(p1 >> 32)));
        ulonglong2 t0 = *reinterpret_cast<const ulonglong2*>(Tb + (size_t)j0 * G);
        ulonglong2 t1 = *reinterpret_cast<const ulonglong2*>(Tb + (size_t)j1 * G);
        FMA2(acc0, t0.x, v0);
        FMA2(acc1, t0.y, v0);
        FMA2(acc0, t1.x, v1);
        FMA2(acc1, t1.y, v1);
    }
    if (e < cnt) {
        ull p0 = L[e];
        int j0 = (int)(unsigned)p0;
        ull v0 = pk2(__uint_as_float((unsigned)(p0 >> 32)), __uint_as_float((unsigned)(p0 >> 32)));
        ulonglong2 t0 = *reinterpret_cast<const ulonglong2*>(Tb + (size_t)j0 * G);
        FMA2(acc0, t0.x, v0);
        FMA2(acc1, t0.y, v0);
    }
    float h0, h1, h2, h3;
    upk2(acc0, h0, h1);
    upk2(acc1, h2, h3);
    float4 r = make_float4(fmaxf(h0, 0.f), fmaxf(h1, 0.f), fmaxf(h2, 0.f), fmaxf(h3, 0.f));
    *reinterpret_cast<float4*>(O + (size_t)row * G + g0) = r;
}

// ---------------- neighbor max-pool, 4 cols/thread (float4) ----------------
__global__ void k_pool4(const float* __restrict__ H, float* __restrict__ O, int G) {
    int b = blockIdx.y;
    int i = blockIdx.x * blockDim.y + threadIdx.y;
    if (i >= NN) return;
    int row = b * NN + i;
    int g0 = threadIdx.x * 4;

    int cnt = g_pl_cnt[row];
    const int* ji = g_pl_idx + (size_t)row * NN;
    const float4* Hb = reinterpret_cast<const float4*>(H + (size_t)b * NN * G + g0);
    int pitch = G >> 2;

    float4 m = make_float4(0.f, 0.f, 0.f, 0.f);   // H >= 0 post-relu
    int e = 0;
    for (; e + 2 <= cnt; e += 2) {
        int j0 = ji[e], j1 = ji[e + 1];
        float4 h0 = Hb[(size_t)j0 * pitch];
        float4 h1 = Hb[(size_t)j1 * pitch];
        m.x = fmaxf(m.x, fmaxf(h0.x, h1.x));
        m.y = fmaxf(m.y, fmaxf(h0.y, h1.y));
        m.z = fmaxf(m.z, fmaxf(h0.z, h1.z));
        m.w = fmaxf(m.w, fmaxf(h0.w, h1.w));
    }
    if (e < cnt) {
        float4 h0 = Hb[(size_t)ji[e] * pitch];
        m.x = fmaxf(m.x, h0.x); m.y = fmaxf(m.y, h0.y);
        m.z = fmaxf(m.z, h0.z); m.w = fmaxf(m.w, h0.w);
    }
    reinterpret_cast<float4*>(O + (size_t)row * G + g0)[0] = m;
}

// ---------------- fused tail: gc3 spmm+relu, pool, gc4, fc1, fin, sigmoid --
__global__ void k_last(const float* __restrict__ T3, const float* __restrict__ gc3_b,
                       const float* __restrict__ gc4_w, const float* __restrict__ gc4_b,
                       const float* __restrict__ fc1_w, const float* __restrict__ fc1_b,
                       const float* __restrict__ fin_w, const float* __restrict__ fin_b,
                       float* __restrict__ out) {
    int b = blockIdx.x;
    int t = threadIdx.x;
    extern __shared__ float sm[];
    float* sT = sm;             // [133][76]
    float* sH = sm + NN * 76;   // [133][76]
    __shared__ float t4[NN];
    __shared__ float hh[NN];
    __shared__ float rr[3];

    for (int idx = t; idx < NN * F0; idx += blockDim.x) {
        int r = idx / F0, k = idx - r * F0;
        sT[r * 76 + k] = T3[(size_t)(b * NN + r) * F0 + k];
    }
    __syncthreads();

    int col = t % 76;
    int rg  = t / 76;
    bool cok = (t < 228) && (col < F0);

    if (t < 228) {
        float bv = cok ? gc3_b[col] : 0.0f;
        for (int r = rg; r < NN; r += 3) {
            int row = b * NN + r;
            int cnt = g_nz_cnt[row];
            const ull* L = g_nz + (size_t)row * NN;
            float acc = bv;
            for (int e = 0; e < cnt; e++) {
                ull p = L[e];
                acc = fmaf(__uint_as_float((unsigned)(p >> 32)),
                           sT[(int)(unsigned)p * 76 + col], acc);
            }
            sH[r * 76 + col] = fmaxf(acc, 0.0f);
        }
    }
    __syncthreads();

    if (t < 228) {
        for (int r = rg; r < NN; r += 3) {
            int row = b * NN + r;
            int cnt = g_pl_cnt[row];
            const int* ji = g_pl_idx + (size_t)row * NN;
            float m = 0.0f;
            for (int e = 0; e < cnt; e++)
                m = fmaxf(m, sH[ji[e] * 76 + col]);
            sT[r * 76 + col] = m;
        }
    }
    __syncthreads();

    if (t < NN) {
        float a = 0.0f;
        #pragma unroll
        for (int k = 0; k < F0; k++) a = fmaf(sT[t * 76 + k], gc4_w[k], a);
        t4[t] = a;
    }
    __syncthreads();

    if (t < NN) {
        int row = b * NN + t;
        int cnt = g_nz_cnt[row];
        const ull* L = g_nz + (size_t)row * NN;
        float acc = gc4_b[0];
        for (int e = 0; e < cnt; e++) {
            ull p = L[e];
            acc = fmaf(__uint_as_float((unsigned)(p >> 32)), t4[(int)(unsigned)p], acc);
        }
        hh[t] = fmaxf(acc, 0.0f);
    }
    __syncthreads();

    if (t < 3) {
        float a = fc1_b[t];
        for (int k = 0; k < NN - 1; k++)
            a = fmaf(hh[k + 1], fc1_w[k * 3 + t], a);
        rr[t] = a;
    }
    __syncthreads();

    if (t == 0) {
        float z = hh[0] * fin_w[0] + rr[0] * fin_w[1] + rr[1] * fin_w[2]
                + rr[2] * fin_w[3] + fin_b[0];
        out[b] = 1.0f / (1.0f + expf(-z));
    }
}

// ---------------- launch ----------------
extern "C" void kernel_launch(void* const* d_in, const int* in_sizes, int n_in,
                              void* d_out, int out_size) {
    const float* x     = (const float*)d_in[0];
    const float* adj   = (const float*)d_in[1];
    const float* emb_w = (const float*)d_in[2];
    const float* emb_b = (const float*)d_in[3];
    const float* gc1_w = (const float*)d_in[4];
    const float* gc1_b = (const float*)d_in[5];
    const float* gc2_w = (const float*)d_in[6];
    const float* gc2_b = (const float*)d_in[7];
    const float* gc3_w = (const float*)d_in[8];
    const float* gc3_b = (const float*)d_in[9];
    const float* gc4_w = (const float*)d_in[10];
    const float* gc4_b = (const float*)d_in[11];
    const float* fc1_w = (const float*)d_in[12];
    const float* fc1_b = (const float*)d_in[13];
    const float* fin_w = (const float*)d_in[14];
    const float* fin_b = (const float*)d_in[15];
    float* out = (float*)d_out;

    float *dA, *dB;
    cudaGetSymbolAddress((void**)&dA, g_bufA);
    cudaGetSymbolAddress((void**)&dB, g_bufB);

    const int GEMM_SMEM = 64 * 128 * 4 + 64 * 64 * 8;   // 65536
    cudaFuncSetAttribute(k_gemm, cudaFuncAttributeMaxDynamicSharedMemorySize, GEMM_SMEM);
    cudaFuncSetAttribute(k_last, cudaFuncAttributeMaxDynamicSharedMemorySize, 84000);

    // 0) sparse lists
    {
        int warps_per_blk = 8;
        int blocks = (NROW + warps_per_blk - 1) / warps_per_blk;
        k_build_lists<<<blocks, warps_per_blk * 32>>>(adj);
    }

    // 1) emb: dA = relu(x @ emb_w + emb_b)   M=8512 K=75  G=150
    k_gemm<<<dim3(67, 3), 128, GEMM_SMEM>>>(x, emb_w, emb_b, dA, NROW, F0, F1, 1);
    // 2) dB = dA @ gc1_w                     K=150 G=256
    k_gemm<<<dim3(67, 4), 128, GEMM_SMEM>>>(dA, gc1_w, nullptr, dB, NROW, F1, H1, 0);
    // 3) dA = relu(adj.dB + gc1_b)
    k_spmm4<<<dim3(34, BB), dim3(64, 4)>>>(dB, gc1_b, dA, H1);
    // 4) dB = pool(dA)
    k_pool4<<<dim3(34, BB), dim3(64, 4)>>>(dA, dB, H1);
    // 5) dA = dB @ gc2_w                     K=256 G=128
    k_gemm<<<dim3(67, 2), 128, GEMM_SMEM>>>(dB, gc2_w, nullptr, dA, NROW, H1, H2, 0);
    // 6) dB = relu(adj.dA + gc2_b)
    k_spmm4<<<dim3(17, BB), dim3(32, 8)>>>(dA, gc2_b, dB, H2);
    // 7) dA = pool(dB)
    k_pool4<<<dim3(17, BB), dim3(32, 8)>>>(dB, dA, H2);
    // 8) dB = dA @ gc3_w                     K=128 G=75
    k_gemm<<<dim3(67, 2), 128, GEMM_SMEM>>>(dA, gc3_w, nullptr, dB, NROW, H2, F0, 0);
    // 9) fused tail
    k_last<<<BB, 256, 2 * NN * 76 * sizeof(float)>>>(dB, gc3_b, gc4_w, gc4_b,
                                                     fc1_w, fc1_b, fin_w, fin_b, out);
}

// round 5
// speedup vs baseline: 1.2721x; 1.2721x over previous
#include <cuda_runtime.h>
#include <math.h>

typedef unsigned long long ull;

// Problem dims
#define BB 64
#define NN 133
#define NROW (BB*NN)      // 8512 = M of all dense GEMMs
#define F0 75
#define F1 150
#define H1 256
#define H2 128

// ---------------- scratch ----------------
__device__ float g_bufA[(size_t)NROW * 256];
__device__ float g_bufB[(size_t)NROW * 256];

__device__ int   g_nz_cnt[NROW];
__device__ ull   g_nz[(size_t)NROW * NN];      // packed {val:hi32, idx:lo32}
__device__ int   g_pl_cnt[NROW];
__device__ int   g_pl_idx[(size_t)NROW * NN];

// ---------------- f32x2 helpers ----------------
__device__ __forceinline__ ull pk2(float x, float y) {
    ull r;
    asm("mov.b64 %0, {%1, %2};" : "=l"(r) : "f"(x), "f"(y));
    return r;
}
__device__ __forceinline__ void upk2(ull v, float& x, float& y) {
    asm("mov.b64 {%0, %1}, %2;" : "=f"(x), "=f"(y) : "l"(v));
}
#define FMA2(acc, a, b) asm("fma.rn.f32x2 %0, %1, %2, %0;" : "+l"(acc) : "l"(a), "l"(b))

// ---------------- build sparse lists from adj (warp per row) ----------------
__global__ void k_build_lists(const float* __restrict__ adj) {
    int warp_in_blk = threadIdx.x >> 5;
    int lane = threadIdx.x & 31;
    int wg = blockIdx.x * (blockDim.x >> 5) + warp_in_blk;
    if (wg >= NROW) return;
    const float* arow = adj + (size_t)wg * NN;

    int cnz = 0, cpl = 0;
    unsigned lt = (1u << lane) - 1u;
    for (int base = 0; base < NN; base += 32) {
        int j = base + lane;
        float a = (j < NN) ? arow[j] : 0.0f;
        bool nz = (j < NN) && (a != 0.0f);
        bool pl = (j < NN) && (a > 1e-5f);
        unsigned mnz = __ballot_sync(0xffffffffu, nz);
        unsigned mpl = __ballot_sync(0xffffffffu, pl);
        if (nz) {
            int pos = cnz + __popc(mnz & lt);
            g_nz[(size_t)wg * NN + pos] =
                ((ull)__float_as_uint(a) << 32) | (unsigned)j;
        }
        if (pl) {
            int pos = cpl + __popc(mpl & lt);
            g_pl_idx[(size_t)wg * NN + pos] = j;
        }
        cnz += __popc(mnz);
        cpl += __popc(mpl);
    }
    if (lane == 0) { g_nz_cnt[wg] = cnz; g_pl_cnt[wg] = cpl; }
}

// ---------------- register-tiled f32x2 SGEMM ----------------
// C[M,G] = A[M,K] @ W[K,G] (+bias, relu). BM=128, BN=64, KC=32.
// Block 128 thr: ty(0..15) -> 8-row strip, tx(0..7) -> 8-col strip.
// sAT padded to pitch 130 (bank-stride 2 on transpose stores, not 0!).
__global__ void k_gemm(const float* __restrict__ A, const float* __restrict__ W,
                       const float* __restrict__ bias, float* __restrict__ C,
                       int M, int K, int G, int do_relu) {
    const int KC = 32;
    const int PA = 130;
    extern __shared__ char smraw[];
    float* sAT = (float*)smraw;                    // [KC][PA]
    ull*   sW2 = (ull*)(smraw + KC * PA * 4);      // [KC][64]

    int t  = threadIdx.x;
    int tx = t & 7;
    int ty = t >> 3;
    int row0 = blockIdx.x * 128;
    int cb   = blockIdx.y * 64;

    ull acc[4][8];
    #pragma unroll
    for (int rp = 0; rp < 4; rp++)
        #pragma unroll
        for (int c = 0; c < 8; c++) acc[rp][c] = 0ull;

    for (int kc = 0; kc < K; kc += KC) {
        // A fill: warp reads one row, 32 consecutive k (coalesced 128B).
        // STS addr stride between lanes = PA floats -> 2-way conflict only.
        #pragma unroll
        for (int rep = 0; rep < 32; rep++) {
            int idx = rep * 128 + t;
            int r  = idx >> 5;
            int kk = idx & 31;
            int k  = kc + kk;
            int row = row0 + r;
            sAT[kk * PA + r] = (row < M && k < K) ? A[(size_t)row * K + k] : 0.0f;
        }
        // W fill: consecutive lanes -> consecutive c (coalesced LDG, clean STS.64)
        #pragma unroll
        for (int rep = 0; rep < 16; rep++) {
            int idx = rep * 128 + t;
            int kk = idx >> 6;
            int c  = idx & 63;
            int k  = kc + kk;
            int g  = cb + c;
            float w = (k < K && g < G) ? W[(size_t)k * G + g] : 0.0f;
            sW2[kk * 64 + c] = pk2(w, w);
        }
        __syncthreads();

        #pragma unroll 4
        for (int kk = 0; kk < KC; kk++) {
            ull a2[4];
            #pragma unroll
            for (int p = 0; p < 4; p++)
                a2[p] = *(const ull*)(sAT + kk * PA + ty * 8 + 2 * p);  // LDS.64
            const ulonglong2* wp = (const ulonglong2*)(sW2 + kk * 64 + tx * 8);
            ulonglong2 w01 = wp[0], w23 = wp[1], w45 = wp[2], w67 = wp[3];
            ull w2[8] = {w01.x, w01.y, w23.x, w23.y, w45.x, w45.y, w67.x, w67.y};
            #pragma unroll
            for (int rp = 0; rp < 4; rp++)
                #pragma unroll
                for (int c = 0; c < 8; c++)
                    FMA2(acc[rp][c], a2[rp], w2[c]);
        }
        __syncthreads();
    }

    // epilogue: bias + relu + store
    #pragma unroll
    for (int c = 0; c < 8; c++) {
        int g = cb + tx * 8 + c;
        if (g >= G) continue;
        float bv = bias ? bias[g] : 0.0f;
        #pragma unroll
        for (int rp = 0; rp < 4; rp++) {
            float v0, v1;
            upk2(acc[rp][c], v0, v1);
            v0 += bv; v1 += bv;
            if (do_relu) { v0 = fmaxf(v0, 0.0f); v1 = fmaxf(v1, 0.0f); }
            int r0 = row0 + ty * 8 + rp * 2;
            if (r0 < M)     C[(size_t)r0 * G + g]       = v0;
            if (r0 + 1 < M) C[(size_t)(r0 + 1) * G + g] = v1;
        }
    }
}

// ---------------- spmm + relu, 4 cols/thread, 4-edge unrolled gather --------
__global__ void k_spmm4(const float* __restrict__ T, const float* __restrict__ bias,
                        float* __restrict__ O, int G) {
    int b = blockIdx.y;
    int i = blockIdx.x * blockDim.y + threadIdx.y;
    if (i >= NN) return;
    int row = b * NN + i;
    int g0 = threadIdx.x * 4;

    int cnt = g_nz_cnt[row];
    const ull* L = g_nz + (size_t)row * NN;
    const float* Tb = T + (size_t)b * NN * G + g0;

    ull acc0 = pk2(bias[g0], bias[g0 + 1]);
    ull acc1 = pk2(bias[g0 + 2], bias[g0 + 3]);
    int e = 0;
    for (; e + 4 <= cnt; e += 4) {
        ull p0 = L[e], p1 = L[e + 1], p2 = L[e + 2], p3 = L[e + 3];
        ulonglong2 t0 = *(const ulonglong2*)(Tb + (size_t)(unsigned)(unsigned)p0 * G);
        ulonglong2 t1 = *(const ulonglong2*)(Tb + (size_t)(unsigned)(unsigned)p1 * G);
        ulonglong2 t2 = *(const ulonglong2*)(Tb + (size_t)(unsigned)(unsigned)p2 * G);
        ulonglong2 t3 = *(const ulonglong2*)(Tb + (size_t)(unsigned)(unsigned)p3 * G);
        float v0 = __uint_as_float((unsigned)(p0 >> 32));
        float v1 = __uint_as_float((unsigned)(p1 >> 32));
        float v2 = __uint_as_float((unsigned)(p2 >> 32));
        float v3 = __uint_as_float((unsigned)(p3 >> 32));
        FMA2(acc0, t0.x, pk2(v0, v0)); FMA2(acc1, t0.y, pk2(v0, v0));
        FMA2(acc0, t1.x, pk2(v1, v1)); FMA2(acc1, t1.y, pk2(v1, v1));
        FMA2(acc0, t2.x, pk2(v2, v2)); FMA2(acc1, t2.y, pk2(v2, v2));
        FMA2(acc0, t3.x, pk2(v3, v3)); FMA2(acc1, t3.y, pk2(v3, v3));
    }
    for (; e < cnt; e++) {
        ull p0 = L[e];
        ulonglong2 t0 = *(const ulonglong2*)(Tb + (size_t)(unsigned)(unsigned)p0 * G);
        float v0 = __uint_as_float((unsigned)(p0 >> 32));
        FMA2(acc0, t0.x, pk2(v0, v0));
        FMA2(acc1, t0.y, pk2(v0, v0));
    }
    float h0, h1, h2, h3;
    upk2(acc0, h0, h1);
    upk2(acc1, h2, h3);
    float4 r = make_float4(fmaxf(h0, 0.f), fmaxf(h1, 0.f), fmaxf(h2, 0.f), fmaxf(h3, 0.f));
    *reinterpret_cast<float4*>(O + (size_t)row * G + g0) = r;
}

// ---------------- neighbor max-pool, 4 cols/thread, 4-edge unrolled ---------
__global__ void k_pool4(const float* __restrict__ H, float* __restrict__ O, int G) {
    int b = blockIdx.y;
    int i = blockIdx.x * blockDim.y + threadIdx.y;
    if (i >= NN) return;
    int row = b * NN + i;
    int g0 = threadIdx.x * 4;

    int cnt = g_pl_cnt[row];
    const int* ji = g_pl_idx + (size_t)row * NN;
    const float4* Hb = reinterpret_cast<const float4*>(H + (size_t)b * NN * G + g0);
    int pitch = G >> 2;

    float4 m = make_float4(0.f, 0.f, 0.f, 0.f);   // H >= 0 post-relu
    int e = 0;
    for (; e + 4 <= cnt; e += 4) {
        int j0 = ji[e], j1 = ji[e + 1], j2 = ji[e + 2], j3 = ji[e + 3];
        float4 h0 = Hb[(size_t)j0 * pitch];
        float4 h1 = Hb[(size_t)j1 * pitch];
        float4 h2 = Hb[(size_t)j2 * pitch];
        float4 h3 = Hb[(size_t)j3 * pitch];
        m.x = fmaxf(m.x, fmaxf(fmaxf(h0.x, h1.x), fmaxf(h2.x, h3.x)));
        m.y = fmaxf(m.y, fmaxf(fmaxf(h0.y, h1.y), fmaxf(h2.y, h3.y)));
        m.z = fmaxf(m.z, fmaxf(fmaxf(h0.z, h1.z), fmaxf(h2.z, h3.z)));
        m.w = fmaxf(m.w, fmaxf(fmaxf(h0.w, h1.w), fmaxf(h2.w, h3.w)));
    }
    for (; e < cnt; e++) {
        float4 h0 = Hb[(size_t)ji[e] * pitch];
        m.x = fmaxf(m.x, h0.x); m.y = fmaxf(m.y, h0.y);
        m.z = fmaxf(m.z, h0.z); m.w = fmaxf(m.w, h0.w);
    }
    reinterpret_cast<float4*>(O + (size_t)row * G + g0)[0] = m;
}

// ---------------- fused tail: gc3 spmm+relu, pool, gc4, fc1, fin, sigmoid --
__global__ void k_last(const float* __restrict__ T3, const float* __restrict__ gc3_b,
                       const float* __restrict__ gc4_w, const float* __restrict__ gc4_b,
                       const float* __restrict__ fc1_w, const float* __restrict__ fc1_b,
                       const float* __restrict__ fin_w, const float* __restrict__ fin_b,
                       float* __restrict__ out) {
    int b = blockIdx.x;
    int t = threadIdx.x;
    extern __shared__ float sm[];
    float* sT = sm;             // [133][76]
    float* sH = sm + NN * 76;   // [133][76]
    __shared__ float t4[NN];
    __shared__ float hh[NN];
    __shared__ float rr[3];

    for (int idx = t; idx < NN * F0; idx += blockDim.x) {
        int r = idx / F0, k = idx - r * F0;
        sT[r * 76 + k] = T3[(size_t)(b * NN + r) * F0 + k];
    }
    __syncthreads();

    int col = t % 76;
    int rg  = t / 76;
    bool cok = (t < 228) && (col < F0);

    if (t < 228) {
        float bv = cok ? gc3_b[col] : 0.0f;
        for (int r = rg; r < NN; r += 3) {
            int row = b * NN + r;
            int cnt = g_nz_cnt[row];
            const ull* L = g_nz + (size_t)row * NN;
            float acc = bv;
            for (int e = 0; e < cnt; e++) {
                ull p = L[e];
                acc = fmaf(__uint_as_float((unsigned)(p >> 32)),
                           sT[(int)(unsigned)p * 76 + col], acc);
            }
            sH[r * 76 + col] = fmaxf(acc, 0.0f);
        }
    }
    __syncthreads();

    if (t < 228) {
        for (int r = rg; r < NN; r += 3) {
            int row = b * NN + r;
            int cnt = g_pl_cnt[row];
            const int* ji = g_pl_idx + (size_t)row * NN;
            float m = 0.0f;
            for (int e = 0; e < cnt; e++)
                m = fmaxf(m, sH[ji[e] * 76 + col]);
            sT[r * 76 + col] = m;
        }
    }
    __syncthreads();

    if (t < NN) {
        float a = 0.0f;
        #pragma unroll
        for (int k = 0; k < F0; k++) a = fmaf(sT[t * 76 + k], gc4_w[k], a);
        t4[t] = a;
    }
    __syncthreads();

    if (t < NN) {
        int row = b * NN + t;
        int cnt = g_nz_cnt[row];
        const ull* L = g_nz + (size_t)row * NN;
        float acc = gc4_b[0];
        for (int e = 0; e < cnt; e++) {
            ull p = L[e];
            acc = fmaf(__uint_as_float((unsigned)(p >> 32)), t4[(int)(unsigned)p], acc);
        }
        hh[t] = fmaxf(acc, 0.0f);
    }
    __syncthreads();

    if (t < 3) {
        float a = fc1_b[t];
        for (int k = 0; k < NN - 1; k++)
            a = fmaf(hh[k + 1], fc1_w[k * 3 + t], a);
        rr[t] = a;
    }
    __syncthreads();

    if (t == 0) {
        float z = hh[0] * fin_w[0] + rr[0] * fin_w[1] + rr[1] * fin_w[2]
                + rr[2] * fin_w[3] + fin_b[0];
        out[b] = 1.0f / (1.0f + expf(-z));
    }
}

// ---------------- launch ----------------
extern "C" void kernel_launch(void* const* d_in, const int* in_sizes, int n_in,
                              void* d_out, int out_size) {
    const float* x     = (const float*)d_in[0];
    const float* adj   = (const float*)d_in[1];
    const float* emb_w = (const float*)d_in[2];
    const float* emb_b = (const float*)d_in[3];
    const float* gc1_w = (const float*)d_in[4];
    const float* gc1_b = (const float*)d_in[5];
    const float* gc2_w = (const float*)d_in[6];
    const float* gc2_b = (const float*)d_in[7];
    const float* gc3_w = (const float*)d_in[8];
    const float* gc3_b = (const float*)d_in[9];
    const float* gc4_w = (const float*)d_in[10];
    const float* gc4_b = (const float*)d_in[11];
    const float* fc1_w = (const float*)d_in[12];
    const float* fc1_b = (const float*)d_in[13];
    const float* fin_w = (const float*)d_in[14];
    const float* fin_b = (const float*)d_in[15];
    float* out = (float*)d_out;

    float *dA, *dB;
    cudaGetSymbolAddress((void**)&dA, g_bufA);
    cudaGetSymbolAddress((void**)&dB, g_bufB);

    const int GEMM_SMEM = 32 * 130 * 4 + 32 * 64 * 8;   // 33024
    cudaFuncSetAttribute(k_gemm, cudaFuncAttributeMaxDynamicSharedMemorySize, GEMM_SMEM);
    cudaFuncSetAttribute(k_last, cudaFuncAttributeMaxDynamicSharedMemorySize, 84000);

    // 0) sparse lists
    {
        int warps_per_blk = 8;
        int blocks = (NROW + warps_per_blk - 1) / warps_per_blk;
        k_build_lists<<<blocks, warps_per_blk * 32>>>(adj);
    }

    // 1) emb: dA = relu(x @ emb_w + emb_b)   M=8512 K=75  G=150
    k_gemm<<<dim3(67, 3), 128, GEMM_SMEM>>>(x, emb_w, emb_b, dA, NROW, F0, F1, 1);
    // 2) dB = dA @ gc1_w                     K=150 G=256
    k_gemm<<<dim3(67, 4), 128, GEMM_SMEM>>>(dA, gc1_w, nullptr, dB, NROW, F1, H1, 0);
    // 3) dA = relu(adj.dB + gc1_b)
    k_spmm4<<<dim3(34, BB), dim3(64, 4)>>>(dB, gc1_b, dA, H1);
    // 4) dB = pool(dA)
    k_pool4<<<dim3(34, BB), dim3(64, 4)>>>(dA, dB, H1);
    // 5) dA = dB @ gc2_w                     K=256 G=128
    k_gemm<<<dim3(67, 2), 128, GEMM_SMEM>>>(dB, gc2_w, nullptr, dA, NROW, H1, H2, 0);
    // 6) dB = relu(adj.dA + gc2_b)
    k_spmm4<<<dim3(17, BB), dim3(32, 8)>>>(dA, gc2_b, dB, H2);
    // 7) dA = pool(dB)
    k_pool4<<<dim3(17, BB), dim3(32, 8)>>>(dB, dA, H2);
    // 8) dB = dA @ gc3_w                     K=128 G=75
    k_gemm<<<dim3(67, 2), 128, GEMM_SMEM>>>(dA, gc3_w, nullptr, dB, NROW, H2, F0, 0);
    // 9) fused tail
    k_last<<<BB, 256, 2 * NN * 76 * sizeof(float)>>>(dB, gc3_b, gc4_w, gc4_b,
                                                     fc1_w, fc1_b, fin_w, fin_b, out);
}

// round 6
// speedup vs baseline: 1.7135x; 1.3469x over previous
#include <cuda_runtime.h>
#include <math.h>

typedef unsigned long long ull;

// Problem dims
#define BB 64
#define NN 133
#define NROW (BB*NN)
#define F0 75
#define F1 150
#define H1 256
#define H2 128

// ---------------- scratch ----------------
__device__ float g_bufA[(size_t)NROW * 256];
__device__ float g_bufB[(size_t)NROW * 256];

__device__ int   g_nz_cnt[NROW];
__device__ ull   g_nz[(size_t)NROW * NN];      // packed {val:hi32, idx:lo32}
__device__ int   g_pl_cnt[NROW];
__device__ int   g_pl_idx[(size_t)NROW * NN];

// ---------------- f32x2 helpers (sparse kernels only) ----------------
__device__ __forceinline__ ull pk2(float x, float y) {
    ull r;
    asm("mov.b64 %0, {%1, %2};" : "=l"(r) : "f"(x), "f"(y));
    return r;
}
__device__ __forceinline__ void upk2(ull v, float& x, float& y) {
    asm("mov.b64 {%0, %1}, %2;" : "=f"(x), "=f"(y) : "l"(v));
}
#define FMA2(acc, a, b) asm("fma.rn.f32x2 %0, %1, %2, %0;" : "+l"(acc) : "l"(a), "l"(b))

// ---------------- build sparse lists from adj (warp per row) ----------------
__global__ void k_build_lists(const float* __restrict__ adj) {
    int warp_in_blk = threadIdx.x >> 5;
    int lane = threadIdx.x & 31;
    int wg = blockIdx.x * (blockDim.x >> 5) + warp_in_blk;
    if (wg >= NROW) return;
    const float* arow = adj + (size_t)wg * NN;

    int cnz = 0, cpl = 0;
    unsigned lt = (1u << lane) - 1u;
    for (int base = 0; base < NN; base += 32) {
        int j = base + lane;
        float a = (j < NN) ? arow[j] : 0.0f;
        bool nz = (j < NN) && (a != 0.0f);
        bool pl = (j < NN) && (a > 1e-5f);
        unsigned mnz = __ballot_sync(0xffffffffu, nz);
        unsigned mpl = __ballot_sync(0xffffffffu, pl);
        if (nz) {
            int pos = cnz + __popc(mnz & lt);
            g_nz[(size_t)wg * NN + pos] =
                ((ull)__float_as_uint(a) << 32) | (unsigned)j;
        }
        if (pl) {
            int pos = cpl + __popc(mpl & lt);
            g_pl_idx[(size_t)wg * NN + pos] = j;
        }
        cnz += __popc(mnz);
        cpl += __popc(mpl);
    }
    if (lane == 0) { g_nz_cnt[wg] = cnz; g_pl_cnt[wg] = cpl; }
}

// ---------------- dense GEMM (round-1 proven design) ----------------
// C[b,i,g] = A[b,i,:] @ W[:,g] (+bias, relu); grid (19, 64); 7 rows/block;
// thread per output col; A tile in smem; W streamed from L2.
__global__ void k_dense(const float* __restrict__ A, const float* __restrict__ W,
                        const float* __restrict__ bias, float* __restrict__ C,
                        int K, int G, int do_relu) {
    int b  = blockIdx.y;
    int i0 = blockIdx.x * 7;
    extern __shared__ float sA[];               // 7*K floats
    int tot = 7 * K;
    for (int idx = threadIdx.x; idx < tot; idx += blockDim.x) {
        int r = idx / K;
        int k = idx - r * K;
        sA[idx] = A[(size_t)(b * NN + i0 + r) * K + k];
    }
    __syncthreads();

    int g = threadIdx.x;
    if (g >= G) return;

    float acc[7];
    #pragma unroll
    for (int r = 0; r < 7; r++) acc[r] = 0.0f;

    for (int k = 0; k < K; k++) {
        float w = W[(size_t)k * G + g];
        #pragma unroll
        for (int r = 0; r < 7; r++) acc[r] = fmaf(sA[r * K + k], w, acc[r]);
    }
    float bv = bias ? bias[g] : 0.0f;
    #pragma unroll
    for (int r = 0; r < 7; r++) {
        float v = acc[r] + bv;
        if (do_relu) v = fmaxf(v, 0.0f);
        C[(size_t)(b * NN + i0 + r) * G + g] = v;
    }
}

// ---------------- spmm + relu, 4 cols/thread, 4-edge unrolled gather --------
__global__ void k_spmm4(const float* __restrict__ T, const float* __restrict__ bias,
                        float* __restrict__ O, int G) {
    int b = blockIdx.y;
    int i = blockIdx.x * blockDim.y + threadIdx.y;
    if (i >= NN) return;
    int row = b * NN + i;
    int g0 = threadIdx.x * 4;

    int cnt = g_nz_cnt[row];
    const ull* L = g_nz + (size_t)row * NN;
    const float* Tb = T + (size_t)b * NN * G + g0;

    ull acc0 = pk2(bias[g0], bias[g0 + 1]);
    ull acc1 = pk2(bias[g0 + 2], bias[g0 + 3]);
    int e = 0;
    for (; e + 4 <= cnt; e += 4) {
        ull p0 = L[e], p1 = L[e + 1], p2 = L[e + 2], p3 = L[e + 3];
        ulonglong2 t0 = *(const ulonglong2*)(Tb + (size_t)(unsigned)p0 * G);
        ulonglong2 t1 = *(const ulonglong2*)(Tb + (size_t)(unsigned)p1 * G);
        ulonglong2 t2 = *(const ulonglong2*)(Tb + (size_t)(unsigned)p2 * G);
        ulonglong2 t3 = *(const ulonglong2*)(Tb + (size_t)(unsigned)p3 * G);
        float v0 = __uint_as_float((unsigned)(p0 >> 32));
        float v1 = __uint_as_float((unsigned)(p1 >> 32));
        float v2 = __uint_as_float((unsigned)(p2 >> 32));
        float v3 = __uint_as_float((unsigned)(p3 >> 32));
        FMA2(acc0, t0.x, pk2(v0, v0)); FMA2(acc1, t0.y, pk2(v0, v0));
        FMA2(acc0, t1.x, pk2(v1, v1)); FMA2(acc1, t1.y, pk2(v1, v1));
        FMA2(acc0, t2.x, pk2(v2, v2)); FMA2(acc1, t2.y, pk2(v2, v2));
        FMA2(acc0, t3.x, pk2(v3, v3)); FMA2(acc1, t3.y, pk2(v3, v3));
    }
    for (; e < cnt; e++) {
        ull p0 = L[e];
        ulonglong2 t0 = *(const ulonglong2*)(Tb + (size_t)(unsigned)p0 * G);
        float v0 = __uint_as_float((unsigned)(p0 >> 32));
        FMA2(acc0, t0.x, pk2(v0, v0));
        FMA2(acc1, t0.y, pk2(v0, v0));
    }
    float h0, h1, h2, h3;
    upk2(acc0, h0, h1);
    upk2(acc1, h2, h3);
    float4 r = make_float4(fmaxf(h0, 0.f), fmaxf(h1, 0.f), fmaxf(h2, 0.f), fmaxf(h3, 0.f));
    *reinterpret_cast<float4*>(O + (size_t)row * G + g0) = r;
}

// ---------------- neighbor max-pool, 4 cols/thread, 4-edge unrolled ---------
__global__ void k_pool4(const float* __restrict__ H, float* __restrict__ O, int G) {
    int b = blockIdx.y;
    int i = blockIdx.x * blockDim.y + threadIdx.y;
    if (i >= NN) return;
    int row = b * NN + i;
    int g0 = threadIdx.x * 4;

    int cnt = g_pl_cnt[row];
    const int* ji = g_pl_idx + (size_t)row * NN;
    const float4* Hb = reinterpret_cast<const float4*>(H + (size_t)b * NN * G + g0);
    int pitch = G >> 2;

    float4 m = make_float4(0.f, 0.f, 0.f, 0.f);   // H >= 0 post-relu
    int e = 0;
    for (; e + 4 <= cnt; e += 4) {
        int j0 = ji[e], j1 = ji[e + 1], j2 = ji[e + 2], j3 = ji[e + 3];
        float4 h0 = Hb[(size_t)j0 * pitch];
        float4 h1 = Hb[(size_t)j1 * pitch];
        float4 h2 = Hb[(size_t)j2 * pitch];
        float4 h3 = Hb[(size_t)j3 * pitch];
        m.x = fmaxf(m.x, fmaxf(fmaxf(h0.x, h1.x), fmaxf(h2.x, h3.x)));
        m.y = fmaxf(m.y, fmaxf(fmaxf(h0.y, h1.y), fmaxf(h2.y, h3.y)));
        m.z = fmaxf(m.z, fmaxf(fmaxf(h0.z, h1.z), fmaxf(h2.z, h3.z)));
        m.w = fmaxf(m.w, fmaxf(fmaxf(h0.w, h1.w), fmaxf(h2.w, h3.w)));
    }
    for (; e < cnt; e++) {
        float4 h0 = Hb[(size_t)ji[e] * pitch];
        m.x = fmaxf(m.x, h0.x); m.y = fmaxf(m.y, h0.y);
        m.z = fmaxf(m.z, h0.z); m.w = fmaxf(m.w, h0.w);
    }
    reinterpret_cast<float4*>(O + (size_t)row * G + g0)[0] = m;
}

// ---------------- fused tail: gc3 spmm+relu, pool, gc4, fc1, fin, sigmoid --
__global__ void k_last(const float* __restrict__ T3, const float* __restrict__ gc3_b,
                       const float* __restrict__ gc4_w, const float* __restrict__ gc4_b,
                       const float* __restrict__ fc1_w, const float* __restrict__ fc1_b,
                       const float* __restrict__ fin_w, const float* __restrict__ fin_b,
                       float* __restrict__ out) {
    int b = blockIdx.x;
    int t = threadIdx.x;
    extern __shared__ float sm[];
    float* sT = sm;             // [133][76]
    float* sH = sm + NN * 76;   // [133][76]
    __shared__ float t4[NN];
    __shared__ float hh[NN];
    __shared__ float rr[3];

    for (int idx = t; idx < NN * F0; idx += blockDim.x) {
        int r = idx / F0, k = idx - r * F0;
        sT[r * 76 + k] = T3[(size_t)(b * NN + r) * F0 + k];
    }
    __syncthreads();

    int col = t % 76;
    int rg  = t / 76;
    bool cok = (t < 228) && (col < F0);

    if (t < 228) {
        float bv = cok ? gc3_b[col] : 0.0f;
        for (int r = rg; r < NN; r += 3) {
            int row = b * NN + r;
            int cnt = g_nz_cnt[row];
            const ull* L = g_nz + (size_t)row * NN;
            float acc = bv;
            for (int e = 0; e < cnt; e++) {
                ull p = L[e];
                acc = fmaf(__uint_as_float((unsigned)(p >> 32)),
                           sT[(int)(unsigned)p * 76 + col], acc);
            }
            sH[r * 76 + col] = fmaxf(acc, 0.0f);
        }
    }
    __syncthreads();

    if (t < 228) {
        for (int r = rg; r < NN; r += 3) {
            int row = b * NN + r;
            int cnt = g_pl_cnt[row];
            const int* ji = g_pl_idx + (size_t)row * NN;
            float m = 0.0f;
            for (int e = 0; e < cnt; e++)
                m = fmaxf(m, sH[ji[e] * 76 + col]);
            sT[r * 76 + col] = m;
        }
    }
    __syncthreads();

    if (t < NN) {
        float a = 0.0f;
        #pragma unroll
        for (int k = 0; k < F0; k++) a = fmaf(sT[t * 76 + k], gc4_w[k], a);
        t4[t] = a;
    }
    __syncthreads();

    if (t < NN) {
        int row = b * NN + t;
        int cnt = g_nz_cnt[row];
        const ull* L = g_nz + (size_t)row * NN;
        float acc = gc4_b[0];
        for (int e = 0; e < cnt; e++) {
            ull p = L[e];
            acc = fmaf(__uint_as_float((unsigned)(p >> 32)), t4[(int)(unsigned)p], acc);
        }
        hh[t] = fmaxf(acc, 0.0f);
    }
    __syncthreads();

    if (t < 3) {
        float a = fc1_b[t];
        for (int k = 0; k < NN - 1; k++)
            a = fmaf(hh[k + 1], fc1_w[k * 3 + t], a);
        rr[t] = a;
    }
    __syncthreads();

    if (t == 0) {
        float z = hh[0] * fin_w[0] + rr[0] * fin_w[1] + rr[1] * fin_w[2]
                + rr[2] * fin_w[3] + fin_b[0];
        out[b] = 1.0f / (1.0f + expf(-z));
    }
}

// ---------------- launch ----------------
extern "C" void kernel_launch(void* const* d_in, const int* in_sizes, int n_in,
                              void* d_out, int out_size) {
    const float* x     = (const float*)d_in[0];
    const float* adj   = (const float*)d_in[1];
    const float* emb_w = (const float*)d_in[2];
    const float* emb_b = (const float*)d_in[3];
    const float* gc1_w = (const float*)d_in[4];
    const float* gc1_b = (const float*)d_in[5];
    const float* gc2_w = (const float*)d_in[6];
    const float* gc2_b = (const float*)d_in[7];
    const float* gc3_w = (const float*)d_in[8];
    const float* gc3_b = (const float*)d_in[9];
    const float* gc4_w = (const float*)d_in[10];
    const float* gc4_b = (const float*)d_in[11];
    const float* fc1_w = (const float*)d_in[12];
    const float* fc1_b = (const float*)d_in[13];
    const float* fin_w = (const float*)d_in[14];
    const float* fin_b = (const float*)d_in[15];
    float* out = (float*)d_out;

    float *dA, *dB;
    cudaGetSymbolAddress((void**)&dA, g_bufA);
    cudaGetSymbolAddress((void**)&dB, g_bufB);

    cudaFuncSetAttribute(k_last, cudaFuncAttributeMaxDynamicSharedMemorySize, 84000);

    // 0) sparse lists
    {
        int warps_per_blk = 8;
        int blocks = (NROW + warps_per_blk - 1) / warps_per_blk;
        k_build_lists<<<blocks, warps_per_blk * 32>>>(adj);
    }

    dim3 gdense(19, BB);

    // 1) emb: dA = relu(x @ emb_w + emb_b)   [.,150]
    k_dense<<<gdense, 160, 7 * F0 * sizeof(float)>>>(x, emb_w, emb_b, dA, F0, F1, 1);
    // 2) dB = dA @ gc1_w                     [.,256]
    k_dense<<<gdense, 256, 7 * F1 * sizeof(float)>>>(dA, gc1_w, nullptr, dB, F1, H1, 0);
    // 3) dA = relu(adj.dB + gc1_b)
    k_spmm4<<<dim3(34, BB), dim3(64, 4)>>>(dB, gc1_b, dA, H1);
    // 4) dB = pool(dA)
    k_pool4<<<dim3(34, BB), dim3(64, 4)>>>(dA, dB, H1);
    // 5) dA = dB @ gc2_w                     [.,128]
    k_dense<<<gdense, 128, 7 * H1 * sizeof(float)>>>(dB, gc2_w, nullptr, dA, H1, H2, 0);
    // 6) dB = relu(adj.dA + gc2_b)
    k_spmm4<<<dim3(17, BB), dim3(32, 8)>>>(dA, gc2_b, dB, H2);
    // 7) dA = pool(dB)
    k_pool4<<<dim3(17, BB), dim3(32, 8)>>>(dB, dA, H2);
    // 8) dB = dA @ gc3_w                     [.,75]
    k_dense<<<gdense, 96, 7 * H2 * sizeof(float)>>>(dA, gc3_w, nullptr, dB, H2, F0, 0);
    // 9) fused tail
    k_last<<<BB, 256, 2 * NN * 76 * sizeof(float)>>>(dB, gc3_b, gc4_w, gc4_b,
                                                     fc1_w, fc1_b, fin_w, fin_b, out);
}

// round 7
// speedup vs baseline: 2.2377x; 1.3060x over previous
#include <cuda_runtime.h>
#include <math.h>

typedef unsigned long long ull;

// Problem dims
#define BB 64
#define NN 133
#define NROW (BB*NN)
#define F0 75
#define F1 150
#define H1 256
#define H2 128
#define GP3 76            // padded gc3 output stride (76*4B = 19*16B, float4-aligned)

// ---------------- scratch ----------------
__device__ float g_bufA[(size_t)NROW * 256];
__device__ float g_bufB[(size_t)NROW * 256];
__device__ float g_b3pad[GP3];

__device__ int   g_nz_cnt[NROW];
__device__ ull   g_nz[(size_t)NROW * NN];      // packed {val:hi32, idx:lo32}
__device__ int   g_pl_cnt[NROW];
__device__ int   g_pl_idx[(size_t)NROW * NN];

// ---------------- f32x2 helpers (sparse kernels only) ----------------
__device__ __forceinline__ ull pk2(float x, float y) {
    ull r;
    asm("mov.b64 %0, {%1, %2};" : "=l"(r) : "f"(x), "f"(y));
    return r;
}
__device__ __forceinline__ void upk2(ull v, float& x, float& y) {
    asm("mov.b64 {%0, %1}, %2;" : "=f"(x), "=f"(y) : "l"(v));
}
#define FMA2(acc, a, b) asm("fma.rn.f32x2 %0, %1, %2, %0;" : "+l"(acc) : "l"(a), "l"(b))

// ---------------- build sparse lists from adj (warp per row) ----------------
__global__ void k_build_lists(const float* __restrict__ adj,
                              const float* __restrict__ gc3_b) {
    int warp_in_blk = threadIdx.x >> 5;
    int lane = threadIdx.x & 31;
    int wg = blockIdx.x * (blockDim.x >> 5) + warp_in_blk;
    if (blockIdx.x == 0 && threadIdx.x < GP3)   // pad gc3 bias once
        g_b3pad[threadIdx.x] = (threadIdx.x < F0) ? gc3_b[threadIdx.x] : 0.0f;
    if (wg >= NROW) return;
    const float* arow = adj + (size_t)wg * NN;

    int cnz = 0, cpl = 0;
    unsigned lt = (1u << lane) - 1u;
    for (int base = 0; base < NN; base += 32) {
        int j = base + lane;
        float a = (j < NN) ? arow[j] : 0.0f;
        bool nz = (j < NN) && (a != 0.0f);
        bool pl = (j < NN) && (a > 1e-5f);
        unsigned mnz = __ballot_sync(0xffffffffu, nz);
        unsigned mpl = __ballot_sync(0xffffffffu, pl);
        if (nz) {
            int pos = cnz + __popc(mnz & lt);
            g_nz[(size_t)wg * NN + pos] =
                ((ull)__float_as_uint(a) << 32) | (unsigned)j;
        }
        if (pl) {
            int pos = cpl + __popc(mpl & lt);
            g_pl_idx[(size_t)wg * NN + pos] = j;
        }
        cnz += __popc(mnz);
        cpl += __popc(mpl);
    }
    if (lane == 0) { g_nz_cnt[wg] = cnz; g_pl_cnt[wg] = cpl; }
}

// ---------------- dense GEMM: round-1 structure, 2 cols/thread ----------------
// C[b,i,g] = A[b,i,:] @ W[:,g] (+bias, relu); grid (19, 64); 7 rows/block.
// Thread owns cols g0=2t, g0+1. Output stride GP (>= G; pad cols written 0).
__global__ void k_dense2(const float* __restrict__ A, const float* __restrict__ W,
                         const float* __restrict__ bias, float* __restrict__ C,
                         int K, int G, int GP, int do_relu) {
    int b  = blockIdx.y;
    int i0 = blockIdx.x * 7;
    extern __shared__ float sA[];               // 7*K floats, row-major (fill conflict-free)
    int tot = 7 * K;
    for (int idx = threadIdx.x; idx < tot; idx += blockDim.x) {
        int r = idx / K;
        int k = idx - r * K;
        sA[idx] = A[(size_t)(b * NN + i0 + r) * K + k];
    }
    __syncthreads();

    int g0 = threadIdx.x * 2;
    if (g0 >= G) return;
    bool g1 = (g0 + 1) < G;

    float acc0[7], acc1[7];
    #pragma unroll
    for (int r = 0; r < 7; r++) { acc0[r] = 0.0f; acc1[r] = 0.0f; }

    for (int k = 0; k < K; k++) {
        float w0 = W[(size_t)k * G + g0];
        float w1 = g1 ? W[(size_t)k * G + g0 + 1] : 0.0f;
        #pragma unroll
        for (int r = 0; r < 7; r++) {
            float a = sA[r * K + k];             // warp broadcast
            acc0[r] = fmaf(a, w0, acc0[r]);
            acc1[r] = fmaf(a, w1, acc1[r]);
        }
    }
    float b0 = bias ? bias[g0] : 0.0f;
    float b1 = (bias && g1) ? bias[g0 + 1] : 0.0f;
    #pragma unroll
    for (int r = 0; r < 7; r++) {
        float v0 = acc0[r] + b0;
        float v1 = acc1[r] + b1;
        if (do_relu) { v0 = fmaxf(v0, 0.0f); v1 = fmaxf(v1, 0.0f); }
        size_t base = (size_t)(b * NN + i0 + r) * GP;
        C[base + g0] = v0;
        if (g0 + 1 < GP) C[base + g0 + 1] = v1;   // pad col gets 0
    }
}

// ---------------- spmm + relu, 4 cols/thread, 4-edge unrolled gather --------
__global__ void k_spmm4(const float* __restrict__ T, const float* __restrict__ bias,
                        float* __restrict__ O, int G) {
    int b = blockIdx.y;
    int i = blockIdx.x * blockDim.y + threadIdx.y;
    if (i >= NN) return;
    int row = b * NN + i;
    int g0 = threadIdx.x * 4;

    int cnt = g_nz_cnt[row];
    const ull* L = g_nz + (size_t)row * NN;
    const float* Tb = T + (size_t)b * NN * G + g0;

    ull acc0 = pk2(bias[g0], bias[g0 + 1]);
    ull acc1 = pk2(bias[g0 + 2], bias[g0 + 3]);
    int e = 0;
    for (; e + 4 <= cnt; e += 4) {
        ull p0 = L[e], p1 = L[e + 1], p2 = L[e + 2], p3 = L[e + 3];
        ulonglong2 t0 = *(const ulonglong2*)(Tb + (size_t)(unsigned)p0 * G);
        ulonglong2 t1 = *(const ulonglong2*)(Tb + (size_t)(unsigned)p1 * G);
        ulonglong2 t2 = *(const ulonglong2*)(Tb + (size_t)(unsigned)p2 * G);
        ulonglong2 t3 = *(const ulonglong2*)(Tb + (size_t)(unsigned)p3 * G);
        float v0 = __uint_as_float((unsigned)(p0 >> 32));
        float v1 = __uint_as_float((unsigned)(p1 >> 32));
        float v2 = __uint_as_float((unsigned)(p2 >> 32));
        float v3 = __uint_as_float((unsigned)(p3 >> 32));
        FMA2(acc0, t0.x, pk2(v0, v0)); FMA2(acc1, t0.y, pk2(v0, v0));
        FMA2(acc0, t1.x, pk2(v1, v1)); FMA2(acc1, t1.y, pk2(v1, v1));
        FMA2(acc0, t2.x, pk2(v2, v2)); FMA2(acc1, t2.y, pk2(v2, v2));
        FMA2(acc0, t3.x, pk2(v3, v3)); FMA2(acc1, t3.y, pk2(v3, v3));
    }
    for (; e < cnt; e++) {
        ull p0 = L[e];
        ulonglong2 t0 = *(const ulonglong2*)(Tb + (size_t)(unsigned)p0 * G);
        float v0 = __uint_as_float((unsigned)(p0 >> 32));
        FMA2(acc0, t0.x, pk2(v0, v0));
        FMA2(acc1, t0.y, pk2(v0, v0));
    }
    float h0, h1, h2, h3;
    upk2(acc0, h0, h1);
    upk2(acc1, h2, h3);
    float4 r = make_float4(fmaxf(h0, 0.f), fmaxf(h1, 0.f), fmaxf(h2, 0.f), fmaxf(h3, 0.f));
    *reinterpret_cast<float4*>(O + (size_t)row * G + g0) = r;
}

// ---------------- neighbor max-pool, 4 cols/thread, 4-edge unrolled ---------
__global__ void k_pool4(const float* __restrict__ H, float* __restrict__ O, int G) {
    int b = blockIdx.y;
    int i = blockIdx.x * blockDim.y + threadIdx.y;
    if (i >= NN) return;
    int row = b * NN + i;
    int g0 = threadIdx.x * 4;

    int cnt = g_pl_cnt[row];
    const int* ji = g_pl_idx + (size_t)row * NN;
    const float4* Hb = reinterpret_cast<const float4*>(H + (size_t)b * NN * G + g0);
    int pitch = G >> 2;

    float4 m = make_float4(0.f, 0.f, 0.f, 0.f);   // H >= 0 post-relu
    int e = 0;
    for (; e + 4 <= cnt; e += 4) {
        int j0 = ji[e], j1 = ji[e + 1], j2 = ji[e + 2], j3 = ji[e + 3];
        float4 h0 = Hb[(size_t)j0 * pitch];
        float4 h1 = Hb[(size_t)j1 * pitch];
        float4 h2 = Hb[(size_t)j2 * pitch];
        float4 h3 = Hb[(size_t)j3 * pitch];
        m.x = fmaxf(m.x, fmaxf(fmaxf(h0.x, h1.x), fmaxf(h2.x, h3.x)));
        m.y = fmaxf(m.y, fmaxf(fmaxf(h0.y, h1.y), fmaxf(h2.y, h3.y)));
        m.z = fmaxf(m.z, fmaxf(fmaxf(h0.z, h1.z), fmaxf(h2.z, h3.z)));
        m.w = fmaxf(m.w, fmaxf(fmaxf(h0.w, h1.w), fmaxf(h2.w, h3.w)));
    }
    for (; e < cnt; e++) {
        float4 h0 = Hb[(size_t)ji[e] * pitch];
        m.x = fmaxf(m.x, h0.x); m.y = fmaxf(m.y, h0.y);
        m.z = fmaxf(m.z, h0.z); m.w = fmaxf(m.w, h0.w);
    }
    reinterpret_cast<float4*>(O + (size_t)row * G + g0)[0] = m;
}

// ---------------- head: gc4 + fc1 + fin + sigmoid (round-1 proven) ----------
// P3 has row stride GP3 (=76), valid cols 0..74.
__global__ void k_final(const float* __restrict__ P3,
                        const float* __restrict__ gc4_w,
                        const float* __restrict__ gc4_b,
                        const float* __restrict__ fc1_w,
                        const float* __restrict__ fc1_b,
                        const float* __restrict__ fin_w,
                        const float* __restrict__ fin_b,
                        float* __restrict__ out) {
    int b = blockIdx.x;
    int t = threadIdx.x;
    __shared__ float t4[NN];
    __shared__ float h[NN];
    __shared__ float rr[3];

    if (t < NN) {
        const float* p = P3 + (size_t)(b * NN + t) * GP3;
        float a = 0.0f;
        #pragma unroll
        for (int k = 0; k < F0; k++) a = fmaf(p[k], gc4_w[k], a);
        t4[t] = a;
    }
    __syncthreads();

    if (t < NN) {
        int row = b * NN + t;
        int cnt = g_nz_cnt[row];
        const ull* L = g_nz + (size_t)row * NN;
        float acc = gc4_b[0];
        for (int e = 0; e < cnt; e++) {
            ull p = L[e];
            acc = fmaf(__uint_as_float((unsigned)(p >> 32)), t4[(int)(unsigned)p], acc);
        }
        h[t] = fmaxf(acc, 0.0f);
    }
    __syncthreads();

    if (t < 3) {
        float a = fc1_b[t];
        for (int k = 0; k < NN - 1; k++)
            a = fmaf(h[k + 1], fc1_w[k * 3 + t], a);
        rr[t] = a;
    }
    __syncthreads();

    if (t == 0) {
        float z = h[0] * fin_w[0] + rr[0] * fin_w[1] + rr[1] * fin_w[2]
                + rr[2] * fin_w[3] + fin_b[0];
        out[b] = 1.0f / (1.0f + expf(-z));
    }
}

// ---------------- launch ----------------
extern "C" void kernel_launch(void* const* d_in, const int* in_sizes, int n_in,
                              void* d_out, int out_size) {
    const float* x     = (const float*)d_in[0];
    const float* adj   = (const float*)d_in[1];
    const float* emb_w = (const float*)d_in[2];
    const float* emb_b = (const float*)d_in[3];
    const float* gc1_w = (const float*)d_in[4];
    const float* gc1_b = (const float*)d_in[5];
    const float* gc2_w = (const float*)d_in[6];
    const float* gc2_b = (const float*)d_in[7];
    const float* gc3_w = (const float*)d_in[8];
    const float* gc3_b = (const float*)d_in[9];
    const float* gc4_w = (const float*)d_in[10];
    const float* gc4_b = (const float*)d_in[11];
    const float* fc1_w = (const float*)d_in[12];
    const float* fc1_b = (const float*)d_in[13];
    const float* fin_w = (const float*)d_in[14];
    const float* fin_b = (const float*)d_in[15];
    float* out = (float*)d_out;

    float *dA, *dB, *db3;
    cudaGetSymbolAddress((void**)&dA, g_bufA);
    cudaGetSymbolAddress((void**)&dB, g_bufB);
    cudaGetSymbolAddress((void**)&db3, g_b3pad);

    // 0) sparse lists (+ pad gc3 bias)
    {
        int warps_per_blk = 8;
        int blocks = (NROW + warps_per_blk - 1) / warps_per_blk;
        k_build_lists<<<blocks, warps_per_blk * 32>>>(adj, gc3_b);
    }

    dim3 gdense(19, BB);

    // 1) emb: dA = relu(x @ emb_w + emb_b)   [.,150]
    k_dense2<<<gdense, 75, 7 * F0 * sizeof(float)>>>(x, emb_w, emb_b, dA, F0, F1, F1, 1);
    // 2) dB = dA @ gc1_w                     [.,256]
    k_dense2<<<gdense, 128, 7 * F1 * sizeof(float)>>>(dA, gc1_w, nullptr, dB, F1, H1, H1, 0);
    // 3) dA = relu(adj.dB + gc1_b)
    k_spmm4<<<dim3(34, BB), dim3(64, 4)>>>(dB, gc1_b, dA, H1);
    // 4) dB = pool(dA)
    k_pool4<<<dim3(34, BB), dim3(64, 4)>>>(dA, dB, H1);
    // 5) dA = dB @ gc2_w                     [.,128]
    k_dense2<<<gdense, 64, 7 * H1 * sizeof(float)>>>(dB, gc2_w, nullptr, dA, H1, H2, H2, 0);
    // 6) dB = relu(adj.dA + gc2_b)
    k_spmm4<<<dim3(17, BB), dim3(32, 8)>>>(dA, gc2_b, dB, H2);
    // 7) dA = pool(dB)
    k_pool4<<<dim3(17, BB), dim3(32, 8)>>>(dB, dA, H2);
    // 8) dB = dA @ gc3_w                     [.,75 padded to 76]
    k_dense2<<<gdense, 38, 7 * H2 * sizeof(float)>>>(dA, gc3_w, nullptr, dB, H2, F0, GP3, 0);
    // 9) dA = relu(adj.dB + b3pad)           [.,76]
    k_spmm4<<<dim3(17, BB), dim3(19, 8)>>>(dB, db3, dA, GP3);
    // 10) dB = pool(dA)                      [.,76]
    k_pool4<<<dim3(17, BB), dim3(19, 8)>>>(dA, dB, GP3);
    // 11) head
    k_final<<<BB, 160>>>(dB, gc4_w, gc4_b, fc1_w, fc1_b, fin_w, fin_b, out);
}

// round 8
// speedup vs baseline: 2.2989x; 1.0273x over previous
#include <cuda_runtime.h>
#include <math.h>

typedef unsigned long long ull;

// Problem dims
#define BB 64
#define NN 133
#define NROW (BB*NN)
#define F0 75
#define F1 150
#define H1 256
#define H2 128
#define GP1 152           // padded emb output stride (152*4B %16 == 0)
#define GP3 76            // padded gc3 output stride

// ---------------- scratch ----------------
__device__ float g_bufA[(size_t)NROW * 256];
__device__ float g_bufB[(size_t)NROW * 256];

__device__ float g_embw[F0 * GP1];   // emb_w padded [75,152]
__device__ float g_embb[GP1];
__device__ float g_gc3w[H2 * GP3];   // gc3_w padded [128,76]
__device__ float g_b3pad[GP3];

__device__ int   g_nz_cnt[NROW];
__device__ ull   g_nz[(size_t)NROW * NN];      // packed {val:hi32, idx:lo32}
__device__ int   g_pl_cnt[NROW];
__device__ int   g_pl_idx[(size_t)NROW * NN];

// ---------------- f32x2 helpers (sparse kernels only) ----------------
__device__ __forceinline__ ull pk2(float x, float y) {
    ull r;
    asm("mov.b64 %0, {%1, %2};" : "=l"(r) : "f"(x), "f"(y));
    return r;
}
__device__ __forceinline__ void upk2(ull v, float& x, float& y) {
    asm("mov.b64 {%0, %1}, %2;" : "=f"(x), "=f"(y) : "l"(v));
}
#define FMA2(acc, a, b) asm("fma.rn.f32x2 %0, %1, %2, %0;" : "+l"(acc) : "l"(a), "l"(b))

// ---------------- one-time weight padding ----------------
#define PAD_T0 (F0*GP1)
#define PAD_T1 (PAD_T0 + GP1)
#define PAD_T2 (PAD_T1 + H2*GP3)
#define PAD_T3 (PAD_T2 + GP3)
__global__ void k_pad(const float* __restrict__ emb_w, const float* __restrict__ emb_b,
                      const float* __restrict__ gc3_w, const float* __restrict__ gc3_b) {
    int idx = blockIdx.x * blockDim.x + threadIdx.x;
    if (idx < PAD_T0) {
        int k = idx / GP1, g = idx % GP1;
        g_embw[idx] = (g < F1) ? emb_w[k * F1 + g] : 0.0f;
    } else if (idx < PAD_T1) {
        int g = idx - PAD_T0;
        g_embb[g] = (g < F1) ? emb_b[g] : 0.0f;
    } else if (idx < PAD_T2) {
        int j = idx - PAD_T1;
        int k = j / GP3, g = j % GP3;
        g_gc3w[j] = (g < F0) ? gc3_w[k * F0 + g] : 0.0f;
    } else if (idx < PAD_T3) {
        int g = idx - PAD_T2;
        g_b3pad[g] = (g < F0) ? gc3_b[g] : 0.0f;
    }
}

// ---------------- build sparse lists from adj (warp per row) ----------------
__global__ void k_build_lists(const float* __restrict__ adj) {
    int warp_in_blk = threadIdx.x >> 5;
    int lane = threadIdx.x & 31;
    int wg = blockIdx.x * (blockDim.x >> 5) + warp_in_blk;
    if (wg >= NROW) return;
    const float* arow = adj + (size_t)wg * NN;

    int cnz = 0, cpl = 0;
    unsigned lt = (1u << lane) - 1u;
    for (int base = 0; base < NN; base += 32) {
        int j = base + lane;
        float a = (j < NN) ? arow[j] : 0.0f;
        bool nz = (j < NN) && (a != 0.0f);
        bool pl = (j < NN) && (a > 1e-5f);
        unsigned mnz = __ballot_sync(0xffffffffu, nz);
        unsigned mpl = __ballot_sync(0xffffffffu, pl);
        if (nz) {
            int pos = cnz + __popc(mnz & lt);
            g_nz[(size_t)wg * NN + pos] =
                ((ull)__float_as_uint(a) << 32) | (unsigned)j;
        }
        if (pl) {
            int pos = cpl + __popc(mpl & lt);
            g_pl_idx[(size_t)wg * NN + pos] = j;
        }
        cnz += __popc(mnz);
        cpl += __popc(mpl);
    }
    if (lane == 0) { g_nz_cnt[wg] = cnz; g_pl_cnt[wg] = cpl; }
}

// ---------------- dense GEMM: 4 cols/thread, float4 W loads ----------------
// C[b,i,g] = A[b,i,:] @ W[:,g] (+bias, relu).
// grid (ceil(133/(7*RG)), 64), block (G/4, RG). Thread: 7 rows x 4 cols.
// A row stride AS (>= K); W row stride == G (G%4==0, 16B-aligned rows);
// output stride GP (%4==0).
__global__ void k_dense4(const float* __restrict__ A, const float* __restrict__ W,
                         const float* __restrict__ bias, float* __restrict__ C,
                         int K, int AS, int G, int GP, int do_relu) {
    extern __shared__ float sA[];                // [7*blockDim.y][K]
    int b     = blockIdx.y;
    int nrows = 7 * blockDim.y;
    int rows0 = blockIdx.x * nrows;
    int tid   = threadIdx.y * blockDim.x + threadIdx.x;
    int nthr  = blockDim.x * blockDim.y;

    int tot = nrows * K;
    for (int idx = tid; idx < tot; idx += nthr) {
        int r = idx / K, k = idx - r * K;
        int row = rows0 + r;
        sA[idx] = (row < NN) ? A[(size_t)(b * NN + row) * AS + k] : 0.0f;
    }
    __syncthreads();

    int g0 = threadIdx.x * 4;
    int i0 = threadIdx.y * 7;               // local row base in sA

    float acc[7][4];
    #pragma unroll
    for (int r = 0; r < 7; r++)
        #pragma unroll
        for (int c = 0; c < 4; c++) acc[r][c] = 0.0f;

    const float* sAr = sA + i0 * K;
    #pragma unroll 4
    for (int k = 0; k < K; k++) {
        float4 w = *reinterpret_cast<const float4*>(W + (size_t)k * G + g0);
        #pragma unroll
        for (int r = 0; r < 7; r++) {
            float a = sAr[r * K + k];        // warp broadcast
            acc[r][0] = fmaf(a, w.x, acc[r][0]);
            acc[r][1] = fmaf(a, w.y, acc[r][1]);
            acc[r][2] = fmaf(a, w.z, acc[r][2]);
            acc[r][3] = fmaf(a, w.w, acc[r][3]);
        }
    }

    float4 bv = make_float4(0.f, 0.f, 0.f, 0.f);
    if (bias) bv = *reinterpret_cast<const float4*>(bias + g0);
    #pragma unroll
    for (int r = 0; r < 7; r++) {
        int row = rows0 + i0 + r;
        if (row >= NN) continue;
        float4 v = make_float4(acc[r][0] + bv.x, acc[r][1] + bv.y,
                               acc[r][2] + bv.z, acc[r][3] + bv.w);
        if (do_relu) {
            v.x = fmaxf(v.x, 0.f); v.y = fmaxf(v.y, 0.f);
            v.z = fmaxf(v.z, 0.f); v.w = fmaxf(v.w, 0.f);
        }
        *reinterpret_cast<float4*>(C + (size_t)(b * NN + row) * GP + g0) = v;
    }
}

// ---------------- spmm + relu, 4 cols/thread, 4-edge unrolled gather --------
__global__ void k_spmm4(const float* __restrict__ T, const float* __restrict__ bias,
                        float* __restrict__ O, int G) {
    int b = blockIdx.y;
    int i = blockIdx.x * blockDim.y + threadIdx.y;
    if (i >= NN) return;
    int row = b * NN + i;
    int g0 = threadIdx.x * 4;

    int cnt = g_nz_cnt[row];
    const ull* L = g_nz + (size_t)row * NN;
    const float* Tb = T + (size_t)b * NN * G + g0;

    ull acc0 = pk2(bias[g0], bias[g0 + 1]);
    ull acc1 = pk2(bias[g0 + 2], bias[g0 + 3]);
    int e = 0;
    for (; e + 4 <= cnt; e += 4) {
        ull p0 = L[e], p1 = L[e + 1], p2 = L[e + 2], p3 = L[e + 3];
        ulonglong2 t0 = *(const ulonglong2*)(Tb + (size_t)(unsigned)p0 * G);
        ulonglong2 t1 = *(const ulonglong2*)(Tb + (size_t)(unsigned)p1 * G);
        ulonglong2 t2 = *(const ulonglong2*)(Tb + (size_t)(unsigned)p2 * G);
        ulonglong2 t3 = *(const ulonglong2*)(Tb + (size_t)(unsigned)p3 * G);
        float v0 = __uint_as_float((unsigned)(p0 >> 32));
        float v1 = __uint_as_float((unsigned)(p1 >> 32));
        float v2 = __uint_as_float((unsigned)(p2 >> 32));
        float v3 = __uint_as_float((unsigned)(p3 >> 32));
        FMA2(acc0, t0.x, pk2(v0, v0)); FMA2(acc1, t0.y, pk2(v0, v0));
        FMA2(acc0, t1.x, pk2(v1, v1)); FMA2(acc1, t1.y, pk2(v1, v1));
        FMA2(acc0, t2.x, pk2(v2, v2)); FMA2(acc1, t2.y, pk2(v2, v2));
        FMA2(acc0, t3.x, pk2(v3, v3)); FMA2(acc1, t3.y, pk2(v3, v3));
    }
    for (; e < cnt; e++) {
        ull p0 = L[e];
        ulonglong2 t0 = *(const ulonglong2*)(Tb + (size_t)(unsigned)p0 * G);
        float v0 = __uint_as_float((unsigned)(p0 >> 32));
        FMA2(acc0, t0.x, pk2(v0, v0));
        FMA2(acc1, t0.y, pk2(v0, v0));
    }
    float h0, h1, h2, h3;
    upk2(acc0, h0, h1);
    upk2(acc1, h2, h3);
    float4 r = make_float4(fmaxf(h0, 0.f), fmaxf(h1, 0.f), fmaxf(h2, 0.f), fmaxf(h3, 0.f));
    *reinterpret_cast<float4*>(O + (size_t)row * G + g0) = r;
}

// ---------------- neighbor max-pool, 4 cols/thread, 4-edge unrolled ---------
__global__ void k_pool4(const float* __restrict__ H, float* __restrict__ O, int G) {
    int b = blockIdx.y;
    int i = blockIdx.x * blockDim.y + threadIdx.y;
    if (i >= NN) return;
    int row = b * NN + i;
    int g0 = threadIdx.x * 4;

    int cnt = g_pl_cnt[row];
    const int* ji = g_pl_idx + (size_t)row * NN;
    const float4* Hb = reinterpret_cast<const float4*>(H + (size_t)b * NN * G + g0);
    int pitch = G >> 2;

    float4 m = make_float4(0.f, 0.f, 0.f, 0.f);   // H >= 0 post-relu
    int e = 0;
    for (; e + 4 <= cnt; e += 4) {
        int j0 = ji[e], j1 = ji[e + 1], j2 = ji[e + 2], j3 = ji[e + 3];
        float4 h0 = Hb[(size_t)j0 * pitch];
        float4 h1 = Hb[(size_t)j1 * pitch];
        float4 h2 = Hb[(size_t)j2 * pitch];
        float4 h3 = Hb[(size_t)j3 * pitch];
        m.x = fmaxf(m.x, fmaxf(fmaxf(h0.x, h1.x), fmaxf(h2.x, h3.x)));
        m.y = fmaxf(m.y, fmaxf(fmaxf(h0.y, h1.y), fmaxf(h2.y, h3.y)));
        m.z = fmaxf(m.z, fmaxf(fmaxf(h0.z, h1.z), fmaxf(h2.z, h3.z)));
        m.w = fmaxf(m.w, fmaxf(fmaxf(h0.w, h1.w), fmaxf(h2.w, h3.w)));
    }
    for (; e < cnt; e++) {
        float4 h0 = Hb[(size_t)ji[e] * pitch];
        m.x = fmaxf(m.x, h0.x); m.y = fmaxf(m.y, h0.y);
        m.z = fmaxf(m.z, h0.z); m.w = fmaxf(m.w, h0.w);
    }
    reinterpret_cast<float4*>(O + (size_t)row * G + g0)[0] = m;
}

// ---------------- head: gc4 + fc1 + fin + sigmoid ----------
__global__ void k_final(const float* __restrict__ P3,
                        const float* __restrict__ gc4_w,
                        const float* __restrict__ gc4_b,
                        const float* __restrict__ fc1_w,
                        const float* __restrict__ fc1_b,
                        const float* __restrict__ fin_w,
                        const float* __restrict__ fin_b,
                        float* __restrict__ out) {
    int b = blockIdx.x;
    int t = threadIdx.x;
    __shared__ float t4[NN];
    __shared__ float h[NN];
    __shared__ float rr[3];

    if (t < NN) {
        const float* p = P3 + (size_t)(b * NN + t) * GP3;
        float a = 0.0f;
        #pragma unroll
        for (int k = 0; k < F0; k++) a = fmaf(p[k], gc4_w[k], a);
        t4[t] = a;
    }
    __syncthreads();

    if (t < NN) {
        int row = b * NN + t;
        int cnt = g_nz_cnt[row];
        const ull* L = g_nz + (size_t)row * NN;
        float acc = gc4_b[0];
        for (int e = 0; e < cnt; e++) {
            ull p = L[e];
            acc = fmaf(__uint_as_float((unsigned)(p >> 32)), t4[(int)(unsigned)p], acc);
        }
        h[t] = fmaxf(acc, 0.0f);
    }
    __syncthreads();

    if (t < 3) {
        float a = fc1_b[t];
        for (int k = 0; k < NN - 1; k++)
            a = fmaf(h[k + 1], fc1_w[k * 3 + t], a);
        rr[t] = a;
    }
    __syncthreads();

    if (t == 0) {
        float z = h[0] * fin_w[0] + rr[0] * fin_w[1] + rr[1] * fin_w[2]
                + rr[2] * fin_w[3] + fin_b[0];
        out[b] = 1.0f / (1.0f + expf(-z));
    }
}

// ---------------- launch ----------------
extern "C" void kernel_launch(void* const* d_in, const int* in_sizes, int n_in,
                              void* d_out, int out_size) {
    const float* x     = (const float*)d_in[0];
    const float* adj   = (const float*)d_in[1];
    const float* emb_w = (const float*)d_in[2];
    const float* emb_b = (const float*)d_in[3];
    const float* gc1_w = (const float*)d_in[4];
    const float* gc1_b = (const float*)d_in[5];
    const float* gc2_w = (const float*)d_in[6];
    const float* gc2_b = (const float*)d_in[7];
    const float* gc3_w = (const float*)d_in[8];
    const float* gc3_b = (const float*)d_in[9];
    const float* gc4_w = (const float*)d_in[10];
    const float* gc4_b = (const float*)d_in[11];
    const float* fc1_w = (const float*)d_in[12];
    const float* fc1_b = (const float*)d_in[13];
    const float* fin_w = (const float*)d_in[14];
    const float* fin_b = (const float*)d_in[15];
    float* out = (float*)d_out;

    float *dA, *dB, *dEw, *dEb, *d3w, *db3;
    cudaGetSymbolAddress((void**)&dA,  g_bufA);
    cudaGetSymbolAddress((void**)&dB,  g_bufB);
    cudaGetSymbolAddress((void**)&dEw, g_embw);
    cudaGetSymbolAddress((void**)&dEb, g_embb);
    cudaGetSymbolAddress((void**)&d3w, g_gc3w);
    cudaGetSymbolAddress((void**)&db3, g_b3pad);

    // 0a) pad weights (emb, gc3)
    k_pad<<<(PAD_T3 + 255) / 256, 256>>>(emb_w, emb_b, gc3_w, gc3_b);
    // 0b) sparse lists
    {
        int warps_per_blk = 8;
        int blocks = (NROW + warps_per_blk - 1) / warps_per_blk;
        k_build_lists<<<blocks, warps_per_blk * 32>>>(adj);
    }

    // 1) emb: dA = relu(x @ embw_pad + embb_pad)   [.,152]  (cols 150..151 = 0)
    k_dense4<<<dim3(5, BB), dim3(38, 4), 28 * F0 * 4>>>(x, dEw, dEb, dA, F0, F0, GP1, GP1, 1);
    // 2) dB = dA @ gc1_w                           [.,256]  (A stride 152, K=150)
    k_dense4<<<dim3(10, BB), dim3(64, 2), 14 * F1 * 4>>>(dA, gc1_w, nullptr, dB, F1, GP1, H1, H1, 0);
    // 3) dA = relu(adj.dB + gc1_b)
    k_spmm4<<<dim3(34, BB), dim3(64, 4)>>>(dB, gc1_b, dA, H1);
    // 4) dB = pool(dA)
    k_pool4<<<dim3(34, BB), dim3(64, 4)>>>(dA, dB, H1);
    // 5) dA = dB @ gc2_w                           [.,128]
    k_dense4<<<dim3(10, BB), dim3(32, 2), 14 * H1 * 4>>>(dB, gc2_w, nullptr, dA, H1, H1, H2, H2, 0);
    // 6) dB = relu(adj.dA + gc2_b)
    k_spmm4<<<dim3(17, BB), dim3(32, 8)>>>(dA, gc2_b, dB, H2);
    // 7) dA = pool(dB)
    k_pool4<<<dim3(17, BB), dim3(32, 8)>>>(dB, dA, H2);
    // 8) dB = dA @ gc3w_pad                        [.,76]
    k_dense4<<<dim3(5, BB), dim3(19, 4), 28 * H2 * 4>>>(dA, d3w, nullptr, dB, H2, H2, GP3, GP3, 0);
    // 9) dA = relu(adj.dB + b3pad)                 [.,76]
    k_spmm4<<<dim3(17, BB), dim3(19, 8)>>>(dB, db3, dA, GP3);
    // 10) dB = pool(dA)                            [.,76]
    k_pool4<<<dim3(17, BB), dim3(19, 8)>>>(dA, dB, GP3);
    // 11) head
    k_final<<<BB, 160>>>(dB, gc4_w, gc4_b, fc1_w, fc1_b, fin_w, fin_b, out);
}